// round 14
// baseline (speedup 1.0000x reference)
#include <cuda_runtime.h>
#include <cuda_fp16.h>
#include <math.h>
#include <stdint.h>

#define NTOK 65536            // 16 * 4096
#define DIM 256
#define QKVC 768
#define HID 1024

// ---------------- scratch ----------------------------------------------------
__device__ __half g_lnh  [(size_t)NTOK * DIM];
__device__ __half g_qkvh [(size_t)NTOK * QKVC];
__device__ __half g_attnh[(size_t)NTOK * DIM];
__device__ __half g_mlph [(size_t)NTOK * HID];
__device__ __half g_biash[8 * 64 * 64];
#define WT_QKV 0
#define WT_PROJ (QKVC * DIM)
#define WT_FC1  (WT_PROJ + DIM * DIM)
#define WT_FC2  (WT_FC1 + HID * DIM)
__device__ __half g_wth[WT_FC2 + DIM * HID];

// ---------------- helpers -----------------------------------------------------
__device__ __forceinline__ uint32_t smem_u32(const void* p) {
    return (uint32_t)__cvta_generic_to_shared((void*)p);
}
__device__ __forceinline__ void cp_async16(uint32_t dst, const void* src) {
    asm volatile("cp.async.cg.shared.global [%0], [%1], 16;" :: "r"(dst), "l"(src));
}
__device__ __forceinline__ float gelu_exact(float v) {
    return 0.5f * v * (1.0f + erff(v * 0.70710678118654752f));
}
__device__ __forceinline__ void mma_f16(float* c, const uint32_t* a, const uint32_t* b) {
    asm volatile(
        "mma.sync.aligned.m16n8k16.row.col.f32.f16.f16.f32 "
        "{%0,%1,%2,%3}, {%4,%5,%6,%7}, {%8,%9}, {%0,%1,%2,%3};"
        : "+f"(c[0]), "+f"(c[1]), "+f"(c[2]), "+f"(c[3])
        : "r"(a[0]), "r"(a[1]), "r"(a[2]), "r"(a[3]), "r"(b[0]), "r"(b[1]));
}
__device__ __forceinline__ void ldm_x4(uint32_t* r, uint32_t addr) {
    asm volatile("ldmatrix.sync.aligned.m8n8.x4.shared.b16 {%0,%1,%2,%3}, [%4];"
                 : "=r"(r[0]), "=r"(r[1]), "=r"(r[2]), "=r"(r[3]) : "r"(addr));
}
__device__ __forceinline__ void ldm_x4_t(uint32_t* r, uint32_t addr) {
    asm volatile("ldmatrix.sync.aligned.m8n8.x4.trans.shared.b16 {%0,%1,%2,%3}, [%4];"
                 : "=r"(r[0]), "=r"(r[1]), "=r"(r[2]), "=r"(r[3]) : "r"(addr));
}
__device__ __forceinline__ uint32_t pack_h2(float a, float b) {
    __half2 h = __floats2half2_rn(a, b);
    return *(uint32_t*)&h;
}
__device__ __forceinline__ float2 h2f2(uint32_t u) {
    return __half22float2(*(__half2*)&u);
}

// ---------------- fused prep: 4 weight transposes + bias table ----------------
__global__ void prep_kernel(const float* __restrict__ qkv_w,
                            const float* __restrict__ proj_w,
                            const float* __restrict__ fc1_w,
                            const float* __restrict__ fc2_w,
                            const float* __restrict__ relb,
                            __half* __restrict__ wt, __half* __restrict__ gb) {
    int blk = blockIdx.x;
    int x = threadIdx.x, y = threadIdx.y;
    if (blk >= 768) {
        int h = blk - 768;
        int tid = y * 32 + x;
        #pragma unroll
        for (int it = 0; it < 16; ++it) {
            int e = tid + it * 256;
            int i = e >> 6, j = e & 63;
            int ridx = ((i >> 3) - (j >> 3) + 7) * 15 + ((i & 7) - (j & 7) + 7);
            gb[h * 4096 + e] = __float2half(relb[ridx * 8 + h]);
        }
        return;
    }
    const float* in; __half* out; int R, C, bx, by;
    if (blk < 192)      { in = qkv_w;  out = wt + WT_QKV;  R = DIM; C = QKVC;
                          int i = blk;       bx = (i % 24) * 32; by = (i / 24) * 32; }
    else if (blk < 256) { in = proj_w; out = wt + WT_PROJ; R = DIM; C = DIM;
                          int i = blk - 192; bx = (i % 8) * 32;  by = (i / 8) * 32; }
    else if (blk < 512) { in = fc1_w;  out = wt + WT_FC1;  R = DIM; C = HID;
                          int i = blk - 256; bx = (i % 32) * 32; by = (i / 32) * 32; }
    else                { in = fc2_w;  out = wt + WT_FC2;  R = HID; C = DIM;
                          int i = blk - 512; bx = (i % 8) * 32;  by = (i / 8) * 32; }
    __shared__ float t[32][33];
    #pragma unroll
    for (int j = 0; j < 32; j += 8)
        t[y + j][x] = in[(size_t)(by + y + j) * C + bx + x];
    __syncthreads();
    #pragma unroll
    for (int j = 0; j < 32; j += 8)
        out[(size_t)(bx + y + j) * R + by + x] = __float2half(t[x][y + j]);
}

// ---------------- LayerNorm: one warp per token, fp32 in -> fp16 out ----------
__global__ void ln_kernel(const float* __restrict__ x,
                          const float* __restrict__ g,
                          const float* __restrict__ b,
                          __half* __restrict__ out) {
    int warp = (blockIdx.x * blockDim.x + threadIdx.x) >> 5;
    int lane = threadIdx.x & 31;
    if (warp >= NTOK) return;
    const float* xp = x + (size_t)warp * DIM;
    float4 v0 = *(const float4*)(xp + lane * 4);
    float4 v1 = *(const float4*)(xp + 128 + lane * 4);
    float s  = v0.x + v0.y + v0.z + v0.w + v1.x + v1.y + v1.z + v1.w;
    float ss = v0.x*v0.x + v0.y*v0.y + v0.z*v0.z + v0.w*v0.w
             + v1.x*v1.x + v1.y*v1.y + v1.z*v1.z + v1.w*v1.w;
    #pragma unroll
    for (int o = 16; o > 0; o >>= 1) {
        s  += __shfl_xor_sync(0xffffffffu, s,  o);
        ss += __shfl_xor_sync(0xffffffffu, ss, o);
    }
    float mu  = s * (1.0f / DIM);
    float var = ss * (1.0f / DIM) - mu * mu;
    float inv = rsqrtf(var + 1e-5f);
    float4 g0 = *(const float4*)(g + lane * 4);
    float4 g1 = *(const float4*)(g + 128 + lane * 4);
    float4 b0 = *(const float4*)(b + lane * 4);
    float4 b1 = *(const float4*)(b + 128 + lane * 4);
    __half2 h0 = __floats2half2_rn((v0.x - mu) * inv * g0.x + b0.x,
                                   (v0.y - mu) * inv * g0.y + b0.y);
    __half2 h1 = __floats2half2_rn((v0.z - mu) * inv * g0.z + b0.z,
                                   (v0.w - mu) * inv * g0.w + b0.w);
    __half2 h2 = __floats2half2_rn((v1.x - mu) * inv * g1.x + b1.x,
                                   (v1.y - mu) * inv * g1.y + b1.y);
    __half2 h3 = __floats2half2_rn((v1.z - mu) * inv * g1.z + b1.z,
                                   (v1.w - mu) * inv * g1.w + b1.w);
    __half* op = out + (size_t)warp * DIM;
    ((uint2*)op)[lane]         = make_uint2(*(uint32_t*)&h0, *(uint32_t*)&h1);
    ((uint2*)(op + 128))[lane] = make_uint2(*(uint32_t*)&h2, *(uint32_t*)&h3);
}

// ---------------- fp16 mma.sync GEMM, 128x128 tile, K-chunk 64, 3-stage ring --
#define HSTR 72                             // halves per SMEM row (64 + pad 8)
#define HSTAGE (128 * HSTR)                 // halves per matrix per stage
#define STG    (2 * HSTAGE)                 // halves per stage (A+B)
#define GSM_TOTAL (3 * STG * 2)             // 110592 bytes

template<int EPI, typename OT>
__global__ __launch_bounds__(256, 2)
void tc_gemm(const __half* __restrict__ A, const __half* __restrict__ Bt,
             OT* __restrict__ C, int K, int N,
             const float* __restrict__ bias, const float* __restrict__ res) {
    extern __shared__ __half smh[];
    int tid = threadIdx.x;
    int lane = tid & 31, wid = tid >> 5;
    int warp_m = wid & 3;
    int warp_n = wid >> 2;
    int block_row = blockIdx.y * 128;
    int block_col = blockIdx.x * 128;

    const __half* gA = A  + (size_t)block_row * K;
    const __half* gB = Bt + (size_t)block_col * K;

    // stage chunk c (K=64 wide) into buffer c%3
    auto stage = [&](int c) {
        int s = c % 3;
        int c0 = c * 64;
        uint32_t smA = smem_u32(smh + (size_t)s * STG);
        uint32_t smB = smA + HSTAGE * 2;
        #pragma unroll
        for (int it = 0; it < 4; ++it) {
            int seg = tid + it * 256;           // 0..1023
            int r = seg >> 3, sg = (seg & 7) * 8;
            cp_async16(smA + (uint32_t)(r * HSTR + sg) * 2,
                       gA + (size_t)r * K + c0 + sg);
        }
        #pragma unroll
        for (int it = 0; it < 4; ++it) {
            int seg = tid + it * 256;
            int r = seg >> 3, sg = (seg & 7) * 8;
            cp_async16(smB + (uint32_t)(r * HSTR + sg) * 2,
                       gB + (size_t)r * K + c0 + sg);
        }
        asm volatile("cp.async.commit_group;");
    };

    float acc[2][8][4];
    #pragma unroll
    for (int i = 0; i < 2; i++)
        #pragma unroll
        for (int j = 0; j < 8; j++)
            #pragma unroll
            for (int q = 0; q < 4; q++) acc[i][j][q] = 0.0f;

    const int nch = K >> 6;                 // K=256 -> 4, K=1024 -> 16
    stage(0);
    if (nch > 1) stage(1);

    int ldm_row  = lane & 7;
    int ldm_tile = lane >> 3;
    int a_roff = warp_m * 32 + (ldm_tile & 1) * 8 + ldm_row;
    int a_coff = (ldm_tile >> 1) * 8;
    int b_roff = warp_n * 64 + (ldm_tile >> 1) * 8 + ldm_row;
    int b_coff = (ldm_tile & 1) * 8;

    for (int c = 0; c < nch; ++c) {
        if (c + 1 < nch) {
            asm volatile("cp.async.wait_group 1;");
        } else {
            asm volatile("cp.async.wait_group 0;");
        }
        __syncthreads();
        // issue the c+2 prefetch AFTER the barrier: it writes buffer
        // (c+2)%3 == (c-1)%3, whose last readers finished before this barrier.
        if (c + 2 < nch) stage(c + 2);
        int s = c % 3;
        uint32_t As = smem_u32(smh + (size_t)s * STG);
        uint32_t Bs = As + HSTAGE * 2;
        #pragma unroll
        for (int kh = 0; kh < 4; ++kh) {
            int kk = kh * 16;
            uint32_t a[2][4];
            #pragma unroll
            for (int am = 0; am < 2; ++am)
                ldm_x4(a[am], As + (uint32_t)((a_roff + am * 16) * HSTR + kk + a_coff) * 2);
            uint32_t b[4][4];
            #pragma unroll
            for (int bp = 0; bp < 4; ++bp)
                ldm_x4(b[bp], Bs + (uint32_t)((b_roff + bp * 16) * HSTR + kk + b_coff) * 2);
            #pragma unroll
            for (int am = 0; am < 2; ++am)
                #pragma unroll
                for (int bp = 0; bp < 4; ++bp) {
                    mma_f16(acc[am][2 * bp],     a[am], b[bp]);
                    mma_f16(acc[am][2 * bp + 1], a[am], b[bp] + 2);
                }
        }
    }

    #pragma unroll
    for (int am = 0; am < 2; ++am) {
        int row0 = block_row + warp_m * 32 + am * 16 + (lane >> 2);
        #pragma unroll
        for (int bn = 0; bn < 8; ++bn) {
            int col = block_col + warp_n * 64 + bn * 8 + 2 * (lane & 3);
            float2 v0 = make_float2(acc[am][bn][0], acc[am][bn][1]);
            float2 v1 = make_float2(acc[am][bn][2], acc[am][bn][3]);
            if (EPI >= 1) {
                float bx = bias[col], by = bias[col + 1];
                v0.x += bx; v0.y += by; v1.x += bx; v1.y += by;
            }
            if (EPI == 2) {
                v0.x = gelu_exact(v0.x); v0.y = gelu_exact(v0.y);
                v1.x = gelu_exact(v1.x); v1.y = gelu_exact(v1.y);
            }
            if (EPI == 3) {
                const float2 r0 = *(const float2*)&res[(size_t)row0 * N + col];
                const float2 r1 = *(const float2*)&res[(size_t)(row0 + 8) * N + col];
                v0.x += r0.x; v0.y += r0.y; v1.x += r1.x; v1.y += r1.y;
            }
            if constexpr (sizeof(OT) == 2) {
                __half2 h0 = __floats2half2_rn(v0.x, v0.y);
                __half2 h1 = __floats2half2_rn(v1.x, v1.y);
                *(__half2*)&C[(size_t)row0 * N + col]       = h0;
                *(__half2*)&C[(size_t)(row0 + 8) * N + col] = h1;
            } else {
                *(float2*)&C[(size_t)row0 * N + col]       = v0;
                *(float2*)&C[(size_t)(row0 + 8) * N + col] = v1;
            }
        }
    }
}

// ---------------- tensor-core windowed attention, 2 windows/block --------------
#define QSTR 40
#define BSTR 72

__global__ __launch_bounds__(256)
void attn_kernel(const __half* __restrict__ qkv,
                 const __half* __restrict__ gbias,
                 __half* __restrict__ out) {
    __shared__ __half sQ[2][64][QSTR];
    __shared__ __half sK[2][64][QSTR];
    __shared__ __half sV[2][64][QSTR];
    __shared__ __half sB[64][BSTR];

    int h  = blockIdx.y;
    int tid = threadIdx.x;
    int lane = tid & 31, w = tid >> 5;
    int widx = w >> 2;
    int wl   = w & 3;

    int wi0 = blockIdx.x * 2;
    int tok_row_arr[2];
    #pragma unroll
    for (int v = 0; v < 2; ++v) {
        int wi = wi0 + v;
        int b = wi >> 6, wrem = wi & 63;
        tok_row_arr[v] = b * 4096 + (wrem >> 3) * 8 * 64 + (wrem & 7) * 8;
    }

    {
        int lv = tid >> 7;
        int t2 = tid & 127;
        int t = t2 >> 1;
        int part = (t2 & 1) * 16;
        int gt = tok_row_arr[lv] + (t >> 3) * 64 + (t & 7);
        const __half* src = qkv + (size_t)gt * QKVC + h * 32 + part;
        cp_async16(smem_u32(&sQ[lv][t][part]),     src);
        cp_async16(smem_u32(&sQ[lv][t][part + 8]), src + 8);
        cp_async16(smem_u32(&sK[lv][t][part]),     src + 256);
        cp_async16(smem_u32(&sK[lv][t][part + 8]), src + 264);
        cp_async16(smem_u32(&sV[lv][t][part]),     src + 512);
        cp_async16(smem_u32(&sV[lv][t][part + 8]), src + 520);
    }
    {
        const __half* gb = gbias + h * 4096;
        #pragma unroll
        for (int it = 0; it < 2; ++it) {
            int i8 = tid + it * 256;
            int r = i8 >> 3, c8 = (i8 & 7) * 8;
            cp_async16(smem_u32(&sB[r][c8]), &gb[r * 64 + c8]);
        }
    }
    asm volatile("cp.async.commit_group;");
    asm volatile("cp.async.wait_group 0;");
    __syncthreads();

    int r0 = wl * 16;
    int quad = lane >> 2, tq = lane & 3;
    int r_lo = r0 + quad;
    int ldm_row = lane & 7;
    int ldm_tile = lane >> 3;

    float sacc[8][4];
    #pragma unroll
    for (int a = 0; a < 8; a++)
        #pragma unroll
        for (int q = 0; q < 4; q++) sacc[a][q] = 0.0f;

    #pragma unroll
    for (int kt = 0; kt < 2; ++kt) {
        int k0 = kt * 16;
        uint32_t af[4];
        ldm_x4(af, smem_u32(&sQ[widx][r0 + (ldm_tile & 1) * 8 + ldm_row]
                               [k0 + (ldm_tile >> 1) * 8]));
        #pragma unroll
        for (int ap = 0; ap < 4; ++ap) {
            int n0 = ap * 16;
            uint32_t bf[4];
            ldm_x4(bf, smem_u32(&sK[widx][n0 + (ldm_tile >> 1) * 8 + ldm_row]
                                   [k0 + (ldm_tile & 1) * 8]));
            mma_f16(sacc[2 * ap],     af, bf);
            mma_f16(sacc[2 * ap + 1], af, bf + 2);
        }
    }

    const float scale = 0.17677669529663688f;
    float mx_lo = -1e30f, mx_hi = -1e30f;
    #pragma unroll
    for (int j = 0; j < 4; ++j) {
        uint32_t bfr[4];
        ldm_x4(bfr, smem_u32(&sB[r0 + (ldm_tile & 1) * 8 + ldm_row]
                               [16 * j + (ldm_tile >> 1) * 8]));
        float2 b0 = h2f2(bfr[0]);
        float2 b1 = h2f2(bfr[1]);
        float2 b2 = h2f2(bfr[2]);
        float2 b3 = h2f2(bfr[3]);
        int a0 = 2 * j, a1 = 2 * j + 1;
        sacc[a0][0] = fmaf(sacc[a0][0], scale, b0.x);
        sacc[a0][1] = fmaf(sacc[a0][1], scale, b0.y);
        sacc[a0][2] = fmaf(sacc[a0][2], scale, b1.x);
        sacc[a0][3] = fmaf(sacc[a0][3], scale, b1.y);
        sacc[a1][0] = fmaf(sacc[a1][0], scale, b2.x);
        sacc[a1][1] = fmaf(sacc[a1][1], scale, b2.y);
        sacc[a1][2] = fmaf(sacc[a1][2], scale, b3.x);
        sacc[a1][3] = fmaf(sacc[a1][3], scale, b3.y);
    }
    #pragma unroll
    for (int a = 0; a < 8; ++a) {
        mx_lo = fmaxf(mx_lo, fmaxf(sacc[a][0], sacc[a][1]));
        mx_hi = fmaxf(mx_hi, fmaxf(sacc[a][2], sacc[a][3]));
    }
    #pragma unroll
    for (int o = 1; o <= 2; o <<= 1) {
        mx_lo = fmaxf(mx_lo, __shfl_xor_sync(0xffffffffu, mx_lo, o));
        mx_hi = fmaxf(mx_hi, __shfl_xor_sync(0xffffffffu, mx_hi, o));
    }
    float sum_lo = 0.0f, sum_hi = 0.0f;
    #pragma unroll
    for (int a = 0; a < 8; ++a) {
        sacc[a][0] = __expf(sacc[a][0] - mx_lo);
        sacc[a][1] = __expf(sacc[a][1] - mx_lo);
        sacc[a][2] = __expf(sacc[a][2] - mx_hi);
        sacc[a][3] = __expf(sacc[a][3] - mx_hi);
        sum_lo += sacc[a][0] + sacc[a][1];
        sum_hi += sacc[a][2] + sacc[a][3];
    }
    #pragma unroll
    for (int o = 1; o <= 2; o <<= 1) {
        sum_lo += __shfl_xor_sync(0xffffffffu, sum_lo, o);
        sum_hi += __shfl_xor_sync(0xffffffffu, sum_hi, o);
    }

    float oacc[4][4];
    #pragma unroll
    for (int a = 0; a < 4; a++)
        #pragma unroll
        for (int q = 0; q < 4; q++) oacc[a][q] = 0.0f;

    #pragma unroll
    for (int kt = 0; kt < 4; ++kt) {
        uint32_t ap_[4];
        ap_[0] = pack_h2(sacc[2*kt][0],     sacc[2*kt][1]);
        ap_[1] = pack_h2(sacc[2*kt][2],     sacc[2*kt][3]);
        ap_[2] = pack_h2(sacc[2*kt+1][0],   sacc[2*kt+1][1]);
        ap_[3] = pack_h2(sacc[2*kt+1][2],   sacc[2*kt+1][3]);
        int k0 = kt * 16;
        #pragma unroll
        for (int np = 0; np < 2; ++np) {
            int n0 = np * 16;
            uint32_t bf[4];
            ldm_x4_t(bf, smem_u32(&sV[widx][k0 + (ldm_tile & 1) * 8 + ldm_row]
                                     [n0 + (ldm_tile >> 1) * 8]));
            mma_f16(oacc[2 * np],     ap_, bf);
            mma_f16(oacc[2 * np + 1], ap_, bf + 2);
        }
    }

    float inv_lo = 1.0f / sum_lo, inv_hi = 1.0f / sum_hi;
    int tok_row = tok_row_arr[widx];
    int gt_lo = tok_row + (r_lo >> 3) * 64 + (r_lo & 7);
    int r_hi = r_lo + 8;
    int gt_hi = tok_row + (r_hi >> 3) * 64 + (r_hi & 7);
    #pragma unroll
    for (int a = 0; a < 4; ++a) {
        int col = h * 32 + a * 8 + 2 * tq;
        __half2 lo = __floats2half2_rn(oacc[a][0] * inv_lo, oacc[a][1] * inv_lo);
        __half2 hi = __floats2half2_rn(oacc[a][2] * inv_hi, oacc[a][3] * inv_hi);
        *(__half2*)&out[(size_t)gt_lo * DIM + col] = lo;
        *(__half2*)&out[(size_t)gt_hi * DIM + col] = hi;
    }
}

// ---------------- launch ------------------------------------------------------
extern "C" void kernel_launch(void* const* d_in, const int* in_sizes, int n_in,
                              void* d_out, int out_size) {
    const float* x      = (const float*)d_in[0];
    const float* ln1_g  = (const float*)d_in[3];
    const float* ln1_b  = (const float*)d_in[4];
    const float* qkv_w  = (const float*)d_in[5];
    const float* proj_w = (const float*)d_in[6];
    const float* proj_b = (const float*)d_in[7];
    const float* relb   = (const float*)d_in[8];
    const float* ln2_g  = (const float*)d_in[9];
    const float* ln2_b  = (const float*)d_in[10];
    const float* fc1_w  = (const float*)d_in[11];
    const float* fc1_b  = (const float*)d_in[12];
    const float* fc2_w  = (const float*)d_in[13];
    const float* fc2_b  = (const float*)d_in[14];
    float* out = (float*)d_out;

    __half *p_lnh, *p_qkvh, *p_attnh, *p_mlph, *p_wth, *p_biash;
    cudaGetSymbolAddress((void**)&p_lnh,   g_lnh);
    cudaGetSymbolAddress((void**)&p_qkvh,  g_qkvh);
    cudaGetSymbolAddress((void**)&p_attnh, g_attnh);
    cudaGetSymbolAddress((void**)&p_mlph,  g_mlph);
    cudaGetSymbolAddress((void**)&p_wth,   g_wth);
    cudaGetSymbolAddress((void**)&p_biash, g_biash);

    cudaFuncSetAttribute((const void*)tc_gemm<0, __half>,
                         cudaFuncAttributeMaxDynamicSharedMemorySize, GSM_TOTAL);
    cudaFuncSetAttribute((const void*)tc_gemm<2, __half>,
                         cudaFuncAttributeMaxDynamicSharedMemorySize, GSM_TOTAL);
    cudaFuncSetAttribute((const void*)tc_gemm<3, float>,
                         cudaFuncAttributeMaxDynamicSharedMemorySize, GSM_TOTAL);

    prep_kernel<<<776, dim3(32, 8)>>>(qkv_w, proj_w, fc1_w, fc2_w, relb, p_wth, p_biash);
    // 1. LN1 -> half
    ln_kernel<<<NTOK / 8, 256>>>(x, ln1_g, ln1_b, p_lnh);
    // 2. QKV -> half
    tc_gemm<0, __half><<<dim3(QKVC / 128, NTOK / 128), 256, GSM_TOTAL>>>(
        p_lnh, p_wth + WT_QKV, p_qkvh, DIM, QKVC, nullptr, nullptr);
    // 3. attention -> half
    attn_kernel<<<dim3(512, 8), 256>>>(p_qkvh, p_biash, p_attnh);
    // 4. proj + bias + residual(x) -> out fp32
    tc_gemm<3, float><<<dim3(DIM / 128, NTOK / 128), 256, GSM_TOTAL>>>(
        p_attnh, p_wth + WT_PROJ, out, DIM, DIM, proj_b, x);
    // 5. LN2 -> half
    ln_kernel<<<NTOK / 8, 256>>>(out, ln2_g, ln2_b, p_lnh);
    // 6. fc1 + bias + gelu -> half
    tc_gemm<2, __half><<<dim3(HID / 128, NTOK / 128), 256, GSM_TOTAL>>>(
        p_lnh, p_wth + WT_FC1, p_mlph, DIM, HID, fc1_b, nullptr);
    // 7. fc2 + bias + residual(out) -> out fp32
    tc_gemm<3, float><<<dim3(DIM / 128, NTOK / 128), 256, GSM_TOTAL>>>(
        p_mlph, p_wth + WT_FC2, out, HID, DIM, fc2_b, out);
}

// round 15
// speedup vs baseline: 1.4366x; 1.4366x over previous
#include <cuda_runtime.h>
#include <cuda_fp16.h>
#include <math.h>
#include <stdint.h>

#define NTOK 65536            // 16 * 4096
#define DIM 256
#define QKVC 768
#define HID 1024

// ---------------- scratch ----------------------------------------------------
__device__ __half g_lnh  [(size_t)NTOK * DIM];
__device__ __half g_qkvh [(size_t)NTOK * QKVC];
__device__ __half g_attnh[(size_t)NTOK * DIM];
__device__ __half g_mlph [(size_t)NTOK * HID];
__device__ __half g_biash[8 * 64 * 64];
#define WT_QKV 0
#define WT_PROJ (QKVC * DIM)
#define WT_FC1  (WT_PROJ + DIM * DIM)
#define WT_FC2  (WT_FC1 + HID * DIM)
__device__ __half g_wth[WT_FC2 + DIM * HID];

// ---------------- helpers -----------------------------------------------------
__device__ __forceinline__ uint32_t smem_u32(const void* p) {
    return (uint32_t)__cvta_generic_to_shared((void*)p);
}
__device__ __forceinline__ void cp_async16(uint32_t dst, const void* src) {
    asm volatile("cp.async.cg.shared.global [%0], [%1], 16;" :: "r"(dst), "l"(src));
}
__device__ __forceinline__ float gelu_exact(float v) {
    return 0.5f * v * (1.0f + erff(v * 0.70710678118654752f));
}
__device__ __forceinline__ void mma_f16(float* c, const uint32_t* a, const uint32_t* b) {
    asm volatile(
        "mma.sync.aligned.m16n8k16.row.col.f32.f16.f16.f32 "
        "{%0,%1,%2,%3}, {%4,%5,%6,%7}, {%8,%9}, {%0,%1,%2,%3};"
        : "+f"(c[0]), "+f"(c[1]), "+f"(c[2]), "+f"(c[3])
        : "r"(a[0]), "r"(a[1]), "r"(a[2]), "r"(a[3]), "r"(b[0]), "r"(b[1]));
}
__device__ __forceinline__ void ldm_x4(uint32_t* r, uint32_t addr) {
    asm volatile("ldmatrix.sync.aligned.m8n8.x4.shared.b16 {%0,%1,%2,%3}, [%4];"
                 : "=r"(r[0]), "=r"(r[1]), "=r"(r[2]), "=r"(r[3]) : "r"(addr));
}
__device__ __forceinline__ void ldm_x4_t(uint32_t* r, uint32_t addr) {
    asm volatile("ldmatrix.sync.aligned.m8n8.x4.trans.shared.b16 {%0,%1,%2,%3}, [%4];"
                 : "=r"(r[0]), "=r"(r[1]), "=r"(r[2]), "=r"(r[3]) : "r"(addr));
}
__device__ __forceinline__ uint32_t pack_h2(float a, float b) {
    __half2 h = __floats2half2_rn(a, b);
    return *(uint32_t*)&h;
}
__device__ __forceinline__ float2 h2f2(uint32_t u) {
    return __half22float2(*(__half2*)&u);
}

// ---------------- fused prep: 4 weight transposes + bias table ----------------
__global__ void prep_kernel(const float* __restrict__ qkv_w,
                            const float* __restrict__ proj_w,
                            const float* __restrict__ fc1_w,
                            const float* __restrict__ fc2_w,
                            const float* __restrict__ relb,
                            __half* __restrict__ wt, __half* __restrict__ gb) {
    int blk = blockIdx.x;
    int x = threadIdx.x, y = threadIdx.y;
    if (blk >= 768) {
        int h = blk - 768;
        int tid = y * 32 + x;
        #pragma unroll
        for (int it = 0; it < 16; ++it) {
            int e = tid + it * 256;
            int i = e >> 6, j = e & 63;
            int ridx = ((i >> 3) - (j >> 3) + 7) * 15 + ((i & 7) - (j & 7) + 7);
            gb[h * 4096 + e] = __float2half(relb[ridx * 8 + h]);
        }
        return;
    }
    const float* in; __half* out; int R, C, bx, by;
    if (blk < 192)      { in = qkv_w;  out = wt + WT_QKV;  R = DIM; C = QKVC;
                          int i = blk;       bx = (i % 24) * 32; by = (i / 24) * 32; }
    else if (blk < 256) { in = proj_w; out = wt + WT_PROJ; R = DIM; C = DIM;
                          int i = blk - 192; bx = (i % 8) * 32;  by = (i / 8) * 32; }
    else if (blk < 512) { in = fc1_w;  out = wt + WT_FC1;  R = DIM; C = HID;
                          int i = blk - 256; bx = (i % 32) * 32; by = (i / 32) * 32; }
    else                { in = fc2_w;  out = wt + WT_FC2;  R = HID; C = DIM;
                          int i = blk - 512; bx = (i % 8) * 32;  by = (i / 8) * 32; }
    __shared__ float t[32][33];
    #pragma unroll
    for (int j = 0; j < 32; j += 8)
        t[y + j][x] = in[(size_t)(by + y + j) * C + bx + x];
    __syncthreads();
    #pragma unroll
    for (int j = 0; j < 32; j += 8)
        out[(size_t)(bx + y + j) * R + by + x] = __float2half(t[x][y + j]);
}

// ---------------- LayerNorm: one warp per token, fp32 in -> fp16 out ----------
__global__ void ln_kernel(const float* __restrict__ x,
                          const float* __restrict__ g,
                          const float* __restrict__ b,
                          __half* __restrict__ out) {
    int warp = (blockIdx.x * blockDim.x + threadIdx.x) >> 5;
    int lane = threadIdx.x & 31;
    if (warp >= NTOK) return;
    const float* xp = x + (size_t)warp * DIM;
    float4 v0 = *(const float4*)(xp + lane * 4);
    float4 v1 = *(const float4*)(xp + 128 + lane * 4);
    float s  = v0.x + v0.y + v0.z + v0.w + v1.x + v1.y + v1.z + v1.w;
    float ss = v0.x*v0.x + v0.y*v0.y + v0.z*v0.z + v0.w*v0.w
             + v1.x*v1.x + v1.y*v1.y + v1.z*v1.z + v1.w*v1.w;
    #pragma unroll
    for (int o = 16; o > 0; o >>= 1) {
        s  += __shfl_xor_sync(0xffffffffu, s,  o);
        ss += __shfl_xor_sync(0xffffffffu, ss, o);
    }
    float mu  = s * (1.0f / DIM);
    float var = ss * (1.0f / DIM) - mu * mu;
    float inv = rsqrtf(var + 1e-5f);
    float4 g0 = *(const float4*)(g + lane * 4);
    float4 g1 = *(const float4*)(g + 128 + lane * 4);
    float4 b0 = *(const float4*)(b + lane * 4);
    float4 b1 = *(const float4*)(b + 128 + lane * 4);
    __half2 h0 = __floats2half2_rn((v0.x - mu) * inv * g0.x + b0.x,
                                   (v0.y - mu) * inv * g0.y + b0.y);
    __half2 h1 = __floats2half2_rn((v0.z - mu) * inv * g0.z + b0.z,
                                   (v0.w - mu) * inv * g0.w + b0.w);
    __half2 h2 = __floats2half2_rn((v1.x - mu) * inv * g1.x + b1.x,
                                   (v1.y - mu) * inv * g1.y + b1.y);
    __half2 h3 = __floats2half2_rn((v1.z - mu) * inv * g1.z + b1.z,
                                   (v1.w - mu) * inv * g1.w + b1.w);
    __half* op = out + (size_t)warp * DIM;
    ((uint2*)op)[lane]         = make_uint2(*(uint32_t*)&h0, *(uint32_t*)&h1);
    ((uint2*)(op + 128))[lane] = make_uint2(*(uint32_t*)&h2, *(uint32_t*)&h3);
}

// ---------------- fp16 mma.sync GEMM, 128x128 tile, K-chunk 32, 4-stage ring --
#define HSTR 40
#define HSTAGE (128 * HSTR)
#define STG    (2 * HSTAGE)
#define GSM_TOTAL (4 * STG * 2)             // 81920 bytes

template<int EPI, typename OT>
__global__ __launch_bounds__(256, 2)
void tc_gemm(const __half* __restrict__ A, const __half* __restrict__ Bt,
             OT* __restrict__ C, int K, int N,
             const float* __restrict__ bias, const float* __restrict__ res) {
    extern __shared__ __half smh[];
    int tid = threadIdx.x;
    int lane = tid & 31, wid = tid >> 5;
    int warp_m = wid & 3;
    int warp_n = wid >> 2;
    int block_row = blockIdx.y * 128;
    int block_col = blockIdx.x * 128;

    const __half* gA = A  + (size_t)block_row * K;
    const __half* gB = Bt + (size_t)block_col * K;

    auto stage = [&](int c) {
        int s = c & 3;
        int c0 = c * 32;
        uint32_t smA = smem_u32(smh + (size_t)s * STG);
        uint32_t smB = smA + HSTAGE * 2;
        #pragma unroll
        for (int it = 0; it < 2; ++it) {
            int seg = tid + it * 256;
            int r = seg >> 2, sg = (seg & 3) * 8;
            cp_async16(smA + (uint32_t)(r * HSTR + sg) * 2,
                       gA + (size_t)r * K + c0 + sg);
        }
        #pragma unroll
        for (int it = 0; it < 2; ++it) {
            int seg = tid + it * 256;
            int r = seg >> 2, sg = (seg & 3) * 8;
            cp_async16(smB + (uint32_t)(r * HSTR + sg) * 2,
                       gB + (size_t)r * K + c0 + sg);
        }
        asm volatile("cp.async.commit_group;");
    };

    float acc[2][8][4];
    #pragma unroll
    for (int i = 0; i < 2; i++)
        #pragma unroll
        for (int j = 0; j < 8; j++)
            #pragma unroll
            for (int q = 0; q < 4; q++) acc[i][j][q] = 0.0f;

    const int nch = K >> 5;
    stage(0);
    if (nch > 1) stage(1);

    int ldm_row  = lane & 7;
    int ldm_tile = lane >> 3;
    int a_roff = warp_m * 32 + (ldm_tile & 1) * 8 + ldm_row;
    int a_coff = (ldm_tile >> 1) * 8;
    int b_roff = warp_n * 64 + (ldm_tile >> 1) * 8 + ldm_row;
    int b_coff = (ldm_tile & 1) * 8;

    for (int c = 0; c < nch; ++c) {
        if (c + 2 < nch) {
            stage(c + 2);
            asm volatile("cp.async.wait_group 2;");
        } else if (c + 1 < nch) {
            asm volatile("cp.async.wait_group 1;");
        } else {
            asm volatile("cp.async.wait_group 0;");
        }
        __syncthreads();
        int s = c & 3;
        uint32_t As = smem_u32(smh + (size_t)s * STG);
        uint32_t Bs = As + HSTAGE * 2;
        #pragma unroll
        for (int kh = 0; kh < 2; ++kh) {
            int kk = kh * 16;
            uint32_t a[2][4];
            #pragma unroll
            for (int am = 0; am < 2; ++am)
                ldm_x4(a[am], As + (uint32_t)((a_roff + am * 16) * HSTR + kk + a_coff) * 2);
            uint32_t b[4][4];
            #pragma unroll
            for (int bp = 0; bp < 4; ++bp)
                ldm_x4(b[bp], Bs + (uint32_t)((b_roff + bp * 16) * HSTR + kk + b_coff) * 2);
            #pragma unroll
            for (int am = 0; am < 2; ++am)
                #pragma unroll
                for (int bp = 0; bp < 4; ++bp) {
                    mma_f16(acc[am][2 * bp],     a[am], b[bp]);
                    mma_f16(acc[am][2 * bp + 1], a[am], b[bp] + 2);
                }
        }
    }

    #pragma unroll
    for (int am = 0; am < 2; ++am) {
        int row0 = block_row + warp_m * 32 + am * 16 + (lane >> 2);
        #pragma unroll
        for (int bn = 0; bn < 8; ++bn) {
            int col = block_col + warp_n * 64 + bn * 8 + 2 * (lane & 3);
            float2 v0 = make_float2(acc[am][bn][0], acc[am][bn][1]);
            float2 v1 = make_float2(acc[am][bn][2], acc[am][bn][3]);
            if (EPI >= 1) {
                float bx = bias[col], by = bias[col + 1];
                v0.x += bx; v0.y += by; v1.x += bx; v1.y += by;
            }
            if (EPI == 2) {
                v0.x = gelu_exact(v0.x); v0.y = gelu_exact(v0.y);
                v1.x = gelu_exact(v1.x); v1.y = gelu_exact(v1.y);
            }
            if (EPI == 3) {
                const float2 r0 = *(const float2*)&res[(size_t)row0 * N + col];
                const float2 r1 = *(const float2*)&res[(size_t)(row0 + 8) * N + col];
                v0.x += r0.x; v0.y += r0.y; v1.x += r1.x; v1.y += r1.y;
            }
            if constexpr (sizeof(OT) == 2) {
                __half2 h0 = __floats2half2_rn(v0.x, v0.y);
                __half2 h1 = __floats2half2_rn(v1.x, v1.y);
                *(__half2*)&C[(size_t)row0 * N + col]       = h0;
                *(__half2*)&C[(size_t)(row0 + 8) * N + col] = h1;
            } else {
                *(float2*)&C[(size_t)row0 * N + col]       = v0;
                *(float2*)&C[(size_t)(row0 + 8) * N + col] = v1;
            }
        }
    }
}

// ---------------- tensor-core windowed attention, 2 windows/block --------------
#define QSTR 40
#define BSTR 72

__global__ __launch_bounds__(256)
void attn_kernel(const __half* __restrict__ qkv,
                 const __half* __restrict__ gbias,
                 __half* __restrict__ out) {
    __shared__ __half sQ[2][64][QSTR];
    __shared__ __half sK[2][64][QSTR];
    __shared__ __half sV[2][64][QSTR];
    __shared__ __half sB[64][BSTR];

    int h  = blockIdx.y;
    int tid = threadIdx.x;
    int lane = tid & 31, w = tid >> 5;
    int widx = w >> 2;
    int wl   = w & 3;

    int wi0 = blockIdx.x * 2;
    int tok_row_arr[2];
    #pragma unroll
    for (int v = 0; v < 2; ++v) {
        int wi = wi0 + v;
        int b = wi >> 6, wrem = wi & 63;
        tok_row_arr[v] = b * 4096 + (wrem >> 3) * 8 * 64 + (wrem & 7) * 8;
    }

    {
        int lv = tid >> 7;
        int t2 = tid & 127;
        int t = t2 >> 1;
        int part = (t2 & 1) * 16;
        int gt = tok_row_arr[lv] + (t >> 3) * 64 + (t & 7);
        const __half* src = qkv + (size_t)gt * QKVC + h * 32 + part;
        cp_async16(smem_u32(&sQ[lv][t][part]),     src);
        cp_async16(smem_u32(&sQ[lv][t][part + 8]), src + 8);
        cp_async16(smem_u32(&sK[lv][t][part]),     src + 256);
        cp_async16(smem_u32(&sK[lv][t][part + 8]), src + 264);
        cp_async16(smem_u32(&sV[lv][t][part]),     src + 512);
        cp_async16(smem_u32(&sV[lv][t][part + 8]), src + 520);
    }
    {
        const __half* gb = gbias + h * 4096;
        #pragma unroll
        for (int it = 0; it < 2; ++it) {
            int i8 = tid + it * 256;
            int r = i8 >> 3, c8 = (i8 & 7) * 8;
            cp_async16(smem_u32(&sB[r][c8]), &gb[r * 64 + c8]);
        }
    }
    asm volatile("cp.async.commit_group;");
    asm volatile("cp.async.wait_group 0;");
    __syncthreads();

    int r0 = wl * 16;
    int quad = lane >> 2, tq = lane & 3;
    int r_lo = r0 + quad;
    int ldm_row = lane & 7;
    int ldm_tile = lane >> 3;

    float sacc[8][4];
    #pragma unroll
    for (int a = 0; a < 8; a++)
        #pragma unroll
        for (int q = 0; q < 4; q++) sacc[a][q] = 0.0f;

    #pragma unroll
    for (int kt = 0; kt < 2; ++kt) {
        int k0 = kt * 16;
        uint32_t af[4];
        ldm_x4(af, smem_u32(&sQ[widx][r0 + (ldm_tile & 1) * 8 + ldm_row]
                               [k0 + (ldm_tile >> 1) * 8]));
        #pragma unroll
        for (int ap = 0; ap < 4; ++ap) {
            int n0 = ap * 16;
            uint32_t bf[4];
            ldm_x4(bf, smem_u32(&sK[widx][n0 + (ldm_tile >> 1) * 8 + ldm_row]
                                   [k0 + (ldm_tile & 1) * 8]));
            mma_f16(sacc[2 * ap],     af, bf);
            mma_f16(sacc[2 * ap + 1], af, bf + 2);
        }
    }

    const float scale = 0.17677669529663688f;
    float mx_lo = -1e30f, mx_hi = -1e30f;
    #pragma unroll
    for (int j = 0; j < 4; ++j) {
        uint32_t bfr[4];
        ldm_x4(bfr, smem_u32(&sB[r0 + (ldm_tile & 1) * 8 + ldm_row]
                               [16 * j + (ldm_tile >> 1) * 8]));
        float2 b0 = h2f2(bfr[0]);
        float2 b1 = h2f2(bfr[1]);
        float2 b2 = h2f2(bfr[2]);
        float2 b3 = h2f2(bfr[3]);
        int a0 = 2 * j, a1 = 2 * j + 1;
        sacc[a0][0] = fmaf(sacc[a0][0], scale, b0.x);
        sacc[a0][1] = fmaf(sacc[a0][1], scale, b0.y);
        sacc[a0][2] = fmaf(sacc[a0][2], scale, b1.x);
        sacc[a0][3] = fmaf(sacc[a0][3], scale, b1.y);
        sacc[a1][0] = fmaf(sacc[a1][0], scale, b2.x);
        sacc[a1][1] = fmaf(sacc[a1][1], scale, b2.y);
        sacc[a1][2] = fmaf(sacc[a1][2], scale, b3.x);
        sacc[a1][3] = fmaf(sacc[a1][3], scale, b3.y);
    }
    #pragma unroll
    for (int a = 0; a < 8; ++a) {
        mx_lo = fmaxf(mx_lo, fmaxf(sacc[a][0], sacc[a][1]));
        mx_hi = fmaxf(mx_hi, fmaxf(sacc[a][2], sacc[a][3]));
    }
    #pragma unroll
    for (int o = 1; o <= 2; o <<= 1) {
        mx_lo = fmaxf(mx_lo, __shfl_xor_sync(0xffffffffu, mx_lo, o));
        mx_hi = fmaxf(mx_hi, __shfl_xor_sync(0xffffffffu, mx_hi, o));
    }
    float sum_lo = 0.0f, sum_hi = 0.0f;
    #pragma unroll
    for (int a = 0; a < 8; ++a) {
        sacc[a][0] = __expf(sacc[a][0] - mx_lo);
        sacc[a][1] = __expf(sacc[a][1] - mx_lo);
        sacc[a][2] = __expf(sacc[a][2] - mx_hi);
        sacc[a][3] = __expf(sacc[a][3] - mx_hi);
        sum_lo += sacc[a][0] + sacc[a][1];
        sum_hi += sacc[a][2] + sacc[a][3];
    }
    #pragma unroll
    for (int o = 1; o <= 2; o <<= 1) {
        sum_lo += __shfl_xor_sync(0xffffffffu, sum_lo, o);
        sum_hi += __shfl_xor_sync(0xffffffffu, sum_hi, o);
    }

    float oacc[4][4];
    #pragma unroll
    for (int a = 0; a < 4; a++)
        #pragma unroll
        for (int q = 0; q < 4; q++) oacc[a][q] = 0.0f;

    #pragma unroll
    for (int kt = 0; kt < 4; ++kt) {
        uint32_t ap_[4];
        ap_[0] = pack_h2(sacc[2*kt][0],     sacc[2*kt][1]);
        ap_[1] = pack_h2(sacc[2*kt][2],     sacc[2*kt][3]);
        ap_[2] = pack_h2(sacc[2*kt+1][0],   sacc[2*kt+1][1]);
        ap_[3] = pack_h2(sacc[2*kt+1][2],   sacc[2*kt+1][3]);
        int k0 = kt * 16;
        #pragma unroll
        for (int np = 0; np < 2; ++np) {
            int n0 = np * 16;
            uint32_t bf[4];
            ldm_x4_t(bf, smem_u32(&sV[widx][k0 + (ldm_tile & 1) * 8 + ldm_row]
                                     [n0 + (ldm_tile >> 1) * 8]));
            mma_f16(oacc[2 * np],     ap_, bf);
            mma_f16(oacc[2 * np + 1], ap_, bf + 2);
        }
    }

    float inv_lo = 1.0f / sum_lo, inv_hi = 1.0f / sum_hi;
    int tok_row = tok_row_arr[widx];
    int gt_lo = tok_row + (r_lo >> 3) * 64 + (r_lo & 7);
    int r_hi = r_lo + 8;
    int gt_hi = tok_row + (r_hi >> 3) * 64 + (r_hi & 7);
    #pragma unroll
    for (int a = 0; a < 4; ++a) {
        int col = h * 32 + a * 8 + 2 * tq;
        __half2 lo = __floats2half2_rn(oacc[a][0] * inv_lo, oacc[a][1] * inv_lo);
        __half2 hi = __floats2half2_rn(oacc[a][2] * inv_hi, oacc[a][3] * inv_hi);
        *(__half2*)&out[(size_t)gt_lo * DIM + col] = lo;
        *(__half2*)&out[(size_t)gt_hi * DIM + col] = hi;
    }
}

// ---------------- launch ------------------------------------------------------
extern "C" void kernel_launch(void* const* d_in, const int* in_sizes, int n_in,
                              void* d_out, int out_size) {
    const float* x      = (const float*)d_in[0];
    const float* ln1_g  = (const float*)d_in[3];
    const float* ln1_b  = (const float*)d_in[4];
    const float* qkv_w  = (const float*)d_in[5];
    const float* proj_w = (const float*)d_in[6];
    const float* proj_b = (const float*)d_in[7];
    const float* relb   = (const float*)d_in[8];
    const float* ln2_g  = (const float*)d_in[9];
    const float* ln2_b  = (const float*)d_in[10];
    const float* fc1_w  = (const float*)d_in[11];
    const float* fc1_b  = (const float*)d_in[12];
    const float* fc2_w  = (const float*)d_in[13];
    const float* fc2_b  = (const float*)d_in[14];
    float* out = (float*)d_out;

    __half *p_lnh, *p_qkvh, *p_attnh, *p_mlph, *p_wth, *p_biash;
    cudaGetSymbolAddress((void**)&p_lnh,   g_lnh);
    cudaGetSymbolAddress((void**)&p_qkvh,  g_qkvh);
    cudaGetSymbolAddress((void**)&p_attnh, g_attnh);
    cudaGetSymbolAddress((void**)&p_mlph,  g_mlph);
    cudaGetSymbolAddress((void**)&p_wth,   g_wth);
    cudaGetSymbolAddress((void**)&p_biash, g_biash);

    cudaFuncSetAttribute((const void*)tc_gemm<0, __half>,
                         cudaFuncAttributeMaxDynamicSharedMemorySize, GSM_TOTAL);
    cudaFuncSetAttribute((const void*)tc_gemm<2, __half>,
                         cudaFuncAttributeMaxDynamicSharedMemorySize, GSM_TOTAL);
    cudaFuncSetAttribute((const void*)tc_gemm<3, float>,
                         cudaFuncAttributeMaxDynamicSharedMemorySize, GSM_TOTAL);

    prep_kernel<<<776, dim3(32, 8)>>>(qkv_w, proj_w, fc1_w, fc2_w, relb, p_wth, p_biash);
    // 1. LN1 -> half
    ln_kernel<<<NTOK / 8, 256>>>(x, ln1_g, ln1_b, p_lnh);
    // 2. QKV -> half
    tc_gemm<0, __half><<<dim3(QKVC / 128, NTOK / 128), 256, GSM_TOTAL>>>(
        p_lnh, p_wth + WT_QKV, p_qkvh, DIM, QKVC, nullptr, nullptr);
    // 3. attention -> half
    attn_kernel<<<dim3(512, 8), 256>>>(p_qkvh, p_biash, p_attnh);
    // 4. proj + bias + residual(x) -> out fp32
    tc_gemm<3, float><<<dim3(DIM / 128, NTOK / 128), 256, GSM_TOTAL>>>(
        p_attnh, p_wth + WT_PROJ, out, DIM, DIM, proj_b, x);
    // 5. LN2 -> half
    ln_kernel<<<NTOK / 8, 256>>>(out, ln2_g, ln2_b, p_lnh);
    // 6. fc1 + bias + gelu -> half
    tc_gemm<2, __half><<<dim3(HID / 128, NTOK / 128), 256, GSM_TOTAL>>>(
        p_lnh, p_wth + WT_FC1, p_mlph, DIM, HID, fc1_b, nullptr);
    // 7. fc2 + bias + residual(out) -> out fp32
    tc_gemm<3, float><<<dim3(DIM / 128, NTOK / 128), 256, GSM_TOTAL>>>(
        p_mlph, p_wth + WT_FC2, out, HID, DIM, fc2_b, out);
}

// round 17
// speedup vs baseline: 1.4380x; 1.0009x over previous
#include <cuda_runtime.h>
#include <cuda_fp16.h>
#include <math.h>
#include <stdint.h>

#define NTOK 65536            // 16 * 4096
#define DIM 256
#define QKVC 768
#define HID 1024

// ---------------- scratch ----------------------------------------------------
__device__ __half g_lnh  [(size_t)NTOK * DIM];
__device__ __half g_qkvh [(size_t)NTOK * QKVC];
__device__ __half g_attnh[(size_t)NTOK * DIM];
__device__ __half g_mlph [(size_t)NTOK * HID];
__device__ __half g_biash[8 * 64 * 64];
#define WT_QKV 0
#define WT_PROJ (QKVC * DIM)
#define WT_FC1  (WT_PROJ + DIM * DIM)
#define WT_FC2  (WT_FC1 + HID * DIM)
__device__ __half g_wth[WT_FC2 + DIM * HID];

// ---------------- helpers -----------------------------------------------------
__device__ __forceinline__ uint32_t smem_u32(const void* p) {
    return (uint32_t)__cvta_generic_to_shared((void*)p);
}
__device__ __forceinline__ void cp_async16(uint32_t dst, const void* src) {
    asm volatile("cp.async.cg.shared.global [%0], [%1], 16;" :: "r"(dst), "l"(src));
}
__device__ __forceinline__ float gelu_exact(float v) {
    return 0.5f * v * (1.0f + erff(v * 0.70710678118654752f));
}
__device__ __forceinline__ void mma_f16(float* c, const uint32_t* a, const uint32_t* b) {
    asm volatile(
        "mma.sync.aligned.m16n8k16.row.col.f32.f16.f16.f32 "
        "{%0,%1,%2,%3}, {%4,%5,%6,%7}, {%8,%9}, {%0,%1,%2,%3};"
        : "+f"(c[0]), "+f"(c[1]), "+f"(c[2]), "+f"(c[3])
        : "r"(a[0]), "r"(a[1]), "r"(a[2]), "r"(a[3]), "r"(b[0]), "r"(b[1]));
}
__device__ __forceinline__ void ldm_x4(uint32_t* r, uint32_t addr) {
    asm volatile("ldmatrix.sync.aligned.m8n8.x4.shared.b16 {%0,%1,%2,%3}, [%4];"
                 : "=r"(r[0]), "=r"(r[1]), "=r"(r[2]), "=r"(r[3]) : "r"(addr));
}
__device__ __forceinline__ void ldm_x4_t(uint32_t* r, uint32_t addr) {
    asm volatile("ldmatrix.sync.aligned.m8n8.x4.trans.shared.b16 {%0,%1,%2,%3}, [%4];"
                 : "=r"(r[0]), "=r"(r[1]), "=r"(r[2]), "=r"(r[3]) : "r"(addr));
}
__device__ __forceinline__ uint32_t pack_h2(float a, float b) {
    __half2 h = __floats2half2_rn(a, b);
    return *(uint32_t*)&h;
}
__device__ __forceinline__ float2 h2f2(uint32_t u) {
    return __half22float2(*(__half2*)&u);
}

// ---------------- LN body (one warp per token) ---------------------------------
__device__ __forceinline__ void ln_token(const float* __restrict__ x,
                                         const float* __restrict__ g,
                                         const float* __restrict__ b,
                                         __half* __restrict__ out,
                                         int token, int lane) {
    const float* xp = x + (size_t)token * DIM;
    float4 v0 = *(const float4*)(xp + lane * 4);
    float4 v1 = *(const float4*)(xp + 128 + lane * 4);
    float s  = v0.x + v0.y + v0.z + v0.w + v1.x + v1.y + v1.z + v1.w;
    float ss = v0.x*v0.x + v0.y*v0.y + v0.z*v0.z + v0.w*v0.w
             + v1.x*v1.x + v1.y*v1.y + v1.z*v1.z + v1.w*v1.w;
    #pragma unroll
    for (int o = 16; o > 0; o >>= 1) {
        s  += __shfl_xor_sync(0xffffffffu, s,  o);
        ss += __shfl_xor_sync(0xffffffffu, ss, o);
    }
    float mu  = s * (1.0f / DIM);
    float var = ss * (1.0f / DIM) - mu * mu;
    float inv = rsqrtf(var + 1e-5f);
    float4 g0 = *(const float4*)(g + lane * 4);
    float4 g1 = *(const float4*)(g + 128 + lane * 4);
    float4 b0 = *(const float4*)(b + lane * 4);
    float4 b1 = *(const float4*)(b + 128 + lane * 4);
    __half2 h0 = __floats2half2_rn((v0.x - mu) * inv * g0.x + b0.x,
                                   (v0.y - mu) * inv * g0.y + b0.y);
    __half2 h1 = __floats2half2_rn((v0.z - mu) * inv * g0.z + b0.z,
                                   (v0.w - mu) * inv * g0.w + b0.w);
    __half2 h2 = __floats2half2_rn((v1.x - mu) * inv * g1.x + b1.x,
                                   (v1.y - mu) * inv * g1.y + b1.y);
    __half2 h3 = __floats2half2_rn((v1.z - mu) * inv * g1.z + b1.z,
                                   (v1.w - mu) * inv * g1.w + b1.w);
    __half* op = out + (size_t)token * DIM;
    ((uint2*)op)[lane]         = make_uint2(*(uint32_t*)&h0, *(uint32_t*)&h1);
    ((uint2*)(op + 128))[lane] = make_uint2(*(uint32_t*)&h2, *(uint32_t*)&h3);
}

// ---------------- plain LN kernel (LN2) -----------------------------------------
__global__ void ln_kernel(const float* __restrict__ x,
                          const float* __restrict__ g,
                          const float* __restrict__ b,
                          __half* __restrict__ out) {
    int warp = (blockIdx.x * blockDim.x + threadIdx.x) >> 5;
    int lane = threadIdx.x & 31;
    if (warp >= NTOK) return;
    ln_token(x, g, b, out, warp, lane);
}

// ---------------- LN1 + prep merged: blocks 0..8191 LN, 8192..8967 prep --------
__global__ void ln1_prep_kernel(const float* __restrict__ x,
                                const float* __restrict__ ln1_g,
                                const float* __restrict__ ln1_b,
                                __half* __restrict__ lnh,
                                const float* __restrict__ qkv_w,
                                const float* __restrict__ proj_w,
                                const float* __restrict__ fc1_w,
                                const float* __restrict__ fc2_w,
                                const float* __restrict__ relb,
                                __half* __restrict__ wt, __half* __restrict__ gb) {
    int bx = blockIdx.x;
    int tid = threadIdx.x;
    if (bx < NTOK / 8) {                     // LN1: 8 warps = 8 tokens / block
        int warp = (bx * 256 + tid) >> 5;
        ln_token(x, ln1_g, ln1_b, lnh, warp, tid & 31);
        return;
    }
    int blk = bx - NTOK / 8;                 // prep role (0..775)
    int xx = tid & 31, yy = tid >> 5;
    if (blk >= 768) {                        // bias table
        int h = blk - 768;
        #pragma unroll
        for (int it = 0; it < 16; ++it) {
            int e = tid + it * 256;
            int i = e >> 6, j = e & 63;
            int ridx = ((i >> 3) - (j >> 3) + 7) * 15 + ((i & 7) - (j & 7) + 7);
            gb[h * 4096 + e] = __float2half(relb[ridx * 8 + h]);
        }
        return;
    }
    const float* in; __half* out; int R, C, bxo, byo;
    if (blk < 192)      { in = qkv_w;  out = wt + WT_QKV;  R = DIM; C = QKVC;
                          int i = blk;       bxo = (i % 24) * 32; byo = (i / 24) * 32; }
    else if (blk < 256) { in = proj_w; out = wt + WT_PROJ; R = DIM; C = DIM;
                          int i = blk - 192; bxo = (i % 8) * 32;  byo = (i / 8) * 32; }
    else if (blk < 512) { in = fc1_w;  out = wt + WT_FC1;  R = DIM; C = HID;
                          int i = blk - 256; bxo = (i % 32) * 32; byo = (i / 32) * 32; }
    else                { in = fc2_w;  out = wt + WT_FC2;  R = HID; C = DIM;
                          int i = blk - 512; bxo = (i % 8) * 32;  byo = (i / 8) * 32; }
    __shared__ float t[32][33];
    #pragma unroll
    for (int j = 0; j < 32; j += 8)
        t[yy + j][xx] = in[(size_t)(byo + yy + j) * C + bxo + xx];
    __syncthreads();
    #pragma unroll
    for (int j = 0; j < 32; j += 8)
        out[(size_t)(bxo + yy + j) * R + byo + xx] = __float2half(t[xx][yy + j]);
}

// ---------------- fp16 mma.sync GEMM, 128x128 tile, K-chunk 32, 4-stage ring --
#define HSTR 40
#define HSTAGE (128 * HSTR)
#define STG    (2 * HSTAGE)
#define GSM_TOTAL (4 * STG * 2)             // 81920 bytes

template<int EPI, typename OT>
__global__ __launch_bounds__(256, 2)
void tc_gemm(const __half* __restrict__ A, const __half* __restrict__ Bt,
             OT* __restrict__ C, int K, int N,
             const float* __restrict__ bias, const float* __restrict__ res) {
    extern __shared__ __half smh[];
    int tid = threadIdx.x;
    int lane = tid & 31, wid = tid >> 5;
    int warp_m = wid & 3;
    int warp_n = wid >> 2;
    int block_row = blockIdx.y * 128;
    int block_col = blockIdx.x * 128;

    const __half* gA = A  + (size_t)block_row * K;
    const __half* gB = Bt + (size_t)block_col * K;

    auto stage = [&](int c) {
        int s = c & 3;
        int c0 = c * 32;
        uint32_t smA = smem_u32(smh + (size_t)s * STG);
        uint32_t smB = smA + HSTAGE * 2;
        #pragma unroll
        for (int it = 0; it < 2; ++it) {
            int seg = tid + it * 256;
            int r = seg >> 2, sg = (seg & 3) * 8;
            cp_async16(smA + (uint32_t)(r * HSTR + sg) * 2,
                       gA + (size_t)r * K + c0 + sg);
        }
        #pragma unroll
        for (int it = 0; it < 2; ++it) {
            int seg = tid + it * 256;
            int r = seg >> 2, sg = (seg & 3) * 8;
            cp_async16(smB + (uint32_t)(r * HSTR + sg) * 2,
                       gB + (size_t)r * K + c0 + sg);
        }
        asm volatile("cp.async.commit_group;");
    };

    float acc[2][8][4];
    #pragma unroll
    for (int i = 0; i < 2; i++)
        #pragma unroll
        for (int j = 0; j < 8; j++)
            #pragma unroll
            for (int q = 0; q < 4; q++) acc[i][j][q] = 0.0f;

    const int nch = K >> 5;
    stage(0);
    if (nch > 1) stage(1);

    int ldm_row  = lane & 7;
    int ldm_tile = lane >> 3;
    int a_roff = warp_m * 32 + (ldm_tile & 1) * 8 + ldm_row;
    int a_coff = (ldm_tile >> 1) * 8;
    int b_roff = warp_n * 64 + (ldm_tile >> 1) * 8 + ldm_row;
    int b_coff = (ldm_tile & 1) * 8;

    for (int c = 0; c < nch; ++c) {
        if (c + 2 < nch) {
            stage(c + 2);
            asm volatile("cp.async.wait_group 2;");
        } else if (c + 1 < nch) {
            asm volatile("cp.async.wait_group 1;");
        } else {
            asm volatile("cp.async.wait_group 0;");
        }
        __syncthreads();
        int s = c & 3;
        uint32_t As = smem_u32(smh + (size_t)s * STG);
        uint32_t Bs = As + HSTAGE * 2;
        #pragma unroll
        for (int kh = 0; kh < 2; ++kh) {
            int kk = kh * 16;
            uint32_t a[2][4];
            #pragma unroll
            for (int am = 0; am < 2; ++am)
                ldm_x4(a[am], As + (uint32_t)((a_roff + am * 16) * HSTR + kk + a_coff) * 2);
            uint32_t b[4][4];
            #pragma unroll
            for (int bp = 0; bp < 4; ++bp)
                ldm_x4(b[bp], Bs + (uint32_t)((b_roff + bp * 16) * HSTR + kk + b_coff) * 2);
            #pragma unroll
            for (int am = 0; am < 2; ++am)
                #pragma unroll
                for (int bp = 0; bp < 4; ++bp) {
                    mma_f16(acc[am][2 * bp],     a[am], b[bp]);
                    mma_f16(acc[am][2 * bp + 1], a[am], b[bp] + 2);
                }
        }
    }

    #pragma unroll
    for (int am = 0; am < 2; ++am) {
        int row0 = block_row + warp_m * 32 + am * 16 + (lane >> 2);
        #pragma unroll
        for (int bn = 0; bn < 8; ++bn) {
            int col = block_col + warp_n * 64 + bn * 8 + 2 * (lane & 3);
            float2 v0 = make_float2(acc[am][bn][0], acc[am][bn][1]);
            float2 v1 = make_float2(acc[am][bn][2], acc[am][bn][3]);
            if (EPI >= 1) {
                float bx = bias[col], by = bias[col + 1];
                v0.x += bx; v0.y += by; v1.x += bx; v1.y += by;
            }
            if (EPI == 2) {
                v0.x = gelu_exact(v0.x); v0.y = gelu_exact(v0.y);
                v1.x = gelu_exact(v1.x); v1.y = gelu_exact(v1.y);
            }
            if (EPI == 3) {
                const float2 r0 = *(const float2*)&res[(size_t)row0 * N + col];
                const float2 r1 = *(const float2*)&res[(size_t)(row0 + 8) * N + col];
                v0.x += r0.x; v0.y += r0.y; v1.x += r1.x; v1.y += r1.y;
            }
            if constexpr (sizeof(OT) == 2) {
                __half2 h0 = __floats2half2_rn(v0.x, v0.y);
                __half2 h1 = __floats2half2_rn(v1.x, v1.y);
                *(__half2*)&C[(size_t)row0 * N + col]       = h0;
                *(__half2*)&C[(size_t)(row0 + 8) * N + col] = h1;
            } else {
                *(float2*)&C[(size_t)row0 * N + col]       = v0;
                *(float2*)&C[(size_t)(row0 + 8) * N + col] = v1;
            }
        }
    }
}

// ---------------- tensor-core windowed attention, 2 windows/block --------------
#define QSTR 40
#define BSTR 72   // 64-wide bias rows need stride >= 64; 72 halves = 144 B (16B-aligned)

__global__ __launch_bounds__(256)
void attn_kernel(const __half* __restrict__ qkv,
                 const __half* __restrict__ gbias,
                 __half* __restrict__ out) {
    __shared__ __half sQ[2][64][QSTR];
    __shared__ __half sK[2][64][QSTR];
    __shared__ __half sV[2][64][QSTR];
    __shared__ __half sB[64][BSTR];

    int h  = blockIdx.y;
    int tid = threadIdx.x;
    int lane = tid & 31, w = tid >> 5;
    int widx = w >> 2;
    int wl   = w & 3;

    int wi0 = blockIdx.x * 2;
    int tok_row_arr[2];
    #pragma unroll
    for (int v = 0; v < 2; ++v) {
        int wi = wi0 + v;
        int b = wi >> 6, wrem = wi & 63;
        tok_row_arr[v] = b * 4096 + (wrem >> 3) * 8 * 64 + (wrem & 7) * 8;
    }

    {
        int lv = tid >> 7;
        int t2 = tid & 127;
        int t = t2 >> 1;
        int part = (t2 & 1) * 16;
        int gt = tok_row_arr[lv] + (t >> 3) * 64 + (t & 7);
        const __half* src = qkv + (size_t)gt * QKVC + h * 32 + part;
        cp_async16(smem_u32(&sQ[lv][t][part]),     src);
        cp_async16(smem_u32(&sQ[lv][t][part + 8]), src + 8);
        cp_async16(smem_u32(&sK[lv][t][part]),     src + 256);
        cp_async16(smem_u32(&sK[lv][t][part + 8]), src + 264);
        cp_async16(smem_u32(&sV[lv][t][part]),     src + 512);
        cp_async16(smem_u32(&sV[lv][t][part + 8]), src + 520);
    }
    {
        const __half* gb = gbias + h * 4096;
        #pragma unroll
        for (int it = 0; it < 2; ++it) {
            int i8 = tid + it * 256;
            int r = i8 >> 3, c8 = (i8 & 7) * 8;
            cp_async16(smem_u32(&sB[r][c8]), &gb[r * 64 + c8]);
        }
    }
    asm volatile("cp.async.commit_group;");
    asm volatile("cp.async.wait_group 0;");
    __syncthreads();

    int r0 = wl * 16;
    int quad = lane >> 2, tq = lane & 3;
    int r_lo = r0 + quad;
    int ldm_row = lane & 7;
    int ldm_tile = lane >> 3;

    float sacc[8][4];
    #pragma unroll
    for (int a = 0; a < 8; a++)
        #pragma unroll
        for (int q = 0; q < 4; q++) sacc[a][q] = 0.0f;

    #pragma unroll
    for (int kt = 0; kt < 2; ++kt) {
        int k0 = kt * 16;
        uint32_t af[4];
        ldm_x4(af, smem_u32(&sQ[widx][r0 + (ldm_tile & 1) * 8 + ldm_row]
                               [k0 + (ldm_tile >> 1) * 8]));
        #pragma unroll
        for (int ap = 0; ap < 4; ++ap) {
            int n0 = ap * 16;
            uint32_t bf[4];
            ldm_x4(bf, smem_u32(&sK[widx][n0 + (ldm_tile >> 1) * 8 + ldm_row]
                                   [k0 + (ldm_tile & 1) * 8]));
            mma_f16(sacc[2 * ap],     af, bf);
            mma_f16(sacc[2 * ap + 1], af, bf + 2);
        }
    }

    const float scale = 0.17677669529663688f;
    float mx_lo = -1e30f, mx_hi = -1e30f;
    #pragma unroll
    for (int j = 0; j < 4; ++j) {
        uint32_t bfr[4];
        ldm_x4(bfr, smem_u32(&sB[r0 + (ldm_tile & 1) * 8 + ldm_row]
                               [16 * j + (ldm_tile >> 1) * 8]));
        float2 b0 = h2f2(bfr[0]);
        float2 b1 = h2f2(bfr[1]);
        float2 b2 = h2f2(bfr[2]);
        float2 b3 = h2f2(bfr[3]);
        int a0 = 2 * j, a1 = 2 * j + 1;
        sacc[a0][0] = fmaf(sacc[a0][0], scale, b0.x);
        sacc[a0][1] = fmaf(sacc[a0][1], scale, b0.y);
        sacc[a0][2] = fmaf(sacc[a0][2], scale, b1.x);
        sacc[a0][3] = fmaf(sacc[a0][3], scale, b1.y);
        sacc[a1][0] = fmaf(sacc[a1][0], scale, b2.x);
        sacc[a1][1] = fmaf(sacc[a1][1], scale, b2.y);
        sacc[a1][2] = fmaf(sacc[a1][2], scale, b3.x);
        sacc[a1][3] = fmaf(sacc[a1][3], scale, b3.y);
    }
    #pragma unroll
    for (int a = 0; a < 8; ++a) {
        mx_lo = fmaxf(mx_lo, fmaxf(sacc[a][0], sacc[a][1]));
        mx_hi = fmaxf(mx_hi, fmaxf(sacc[a][2], sacc[a][3]));
    }
    #pragma unroll
    for (int o = 1; o <= 2; o <<= 1) {
        mx_lo = fmaxf(mx_lo, __shfl_xor_sync(0xffffffffu, mx_lo, o));
        mx_hi = fmaxf(mx_hi, __shfl_xor_sync(0xffffffffu, mx_hi, o));
    }
    float sum_lo = 0.0f, sum_hi = 0.0f;
    #pragma unroll
    for (int a = 0; a < 8; ++a) {
        sacc[a][0] = __expf(sacc[a][0] - mx_lo);
        sacc[a][1] = __expf(sacc[a][1] - mx_lo);
        sacc[a][2] = __expf(sacc[a][2] - mx_hi);
        sacc[a][3] = __expf(sacc[a][3] - mx_hi);
        sum_lo += sacc[a][0] + sacc[a][1];
        sum_hi += sacc[a][2] + sacc[a][3];
    }
    #pragma unroll
    for (int o = 1; o <= 2; o <<= 1) {
        sum_lo += __shfl_xor_sync(0xffffffffu, sum_lo, o);
        sum_hi += __shfl_xor_sync(0xffffffffu, sum_hi, o);
    }

    float oacc[4][4];
    #pragma unroll
    for (int a = 0; a < 4; a++)
        #pragma unroll
        for (int q = 0; q < 4; q++) oacc[a][q] = 0.0f;

    #pragma unroll
    for (int kt = 0; kt < 4; ++kt) {
        uint32_t ap_[4];
        ap_[0] = pack_h2(sacc[2*kt][0],     sacc[2*kt][1]);
        ap_[1] = pack_h2(sacc[2*kt][2],     sacc[2*kt][3]);
        ap_[2] = pack_h2(sacc[2*kt+1][0],   sacc[2*kt+1][1]);
        ap_[3] = pack_h2(sacc[2*kt+1][2],   sacc[2*kt+1][3]);
        int k0 = kt * 16;
        #pragma unroll
        for (int np = 0; np < 2; ++np) {
            int n0 = np * 16;
            uint32_t bf[4];
            ldm_x4_t(bf, smem_u32(&sV[widx][k0 + (ldm_tile & 1) * 8 + ldm_row]
                                     [n0 + (ldm_tile >> 1) * 8]));
            mma_f16(oacc[2 * np],     ap_, bf);
            mma_f16(oacc[2 * np + 1], ap_, bf + 2);
        }
    }

    float inv_lo = 1.0f / sum_lo, inv_hi = 1.0f / sum_hi;
    int tok_row = tok_row_arr[widx];
    int gt_lo = tok_row + (r_lo >> 3) * 64 + (r_lo & 7);
    int r_hi = r_lo + 8;
    int gt_hi = tok_row + (r_hi >> 3) * 64 + (r_hi & 7);
    #pragma unroll
    for (int a = 0; a < 4; ++a) {
        int col = h * 32 + a * 8 + 2 * tq;
        __half2 lo = __floats2half2_rn(oacc[a][0] * inv_lo, oacc[a][1] * inv_lo);
        __half2 hi = __floats2half2_rn(oacc[a][2] * inv_hi, oacc[a][3] * inv_hi);
        *(__half2*)&out[(size_t)gt_lo * DIM + col] = lo;
        *(__half2*)&out[(size_t)gt_hi * DIM + col] = hi;
    }
}

// ---------------- launch ------------------------------------------------------
extern "C" void kernel_launch(void* const* d_in, const int* in_sizes, int n_in,
                              void* d_out, int out_size) {
    const float* x      = (const float*)d_in[0];
    const float* ln1_g  = (const float*)d_in[3];
    const float* ln1_b  = (const float*)d_in[4];
    const float* qkv_w  = (const float*)d_in[5];
    const float* proj_w = (const float*)d_in[6];
    const float* proj_b = (const float*)d_in[7];
    const float* relb   = (const float*)d_in[8];
    const float* ln2_g  = (const float*)d_in[9];
    const float* ln2_b  = (const float*)d_in[10];
    const float* fc1_w  = (const float*)d_in[11];
    const float* fc1_b  = (const float*)d_in[12];
    const float* fc2_w  = (const float*)d_in[13];
    const float* fc2_b  = (const float*)d_in[14];
    float* out = (float*)d_out;

    __half *p_lnh, *p_qkvh, *p_attnh, *p_mlph, *p_wth, *p_biash;
    cudaGetSymbolAddress((void**)&p_lnh,   g_lnh);
    cudaGetSymbolAddress((void**)&p_qkvh,  g_qkvh);
    cudaGetSymbolAddress((void**)&p_attnh, g_attnh);
    cudaGetSymbolAddress((void**)&p_mlph,  g_mlph);
    cudaGetSymbolAddress((void**)&p_wth,   g_wth);
    cudaGetSymbolAddress((void**)&p_biash, g_biash);

    cudaFuncSetAttribute((const void*)tc_gemm<0, __half>,
                         cudaFuncAttributeMaxDynamicSharedMemorySize, GSM_TOTAL);
    cudaFuncSetAttribute((const void*)tc_gemm<2, __half>,
                         cudaFuncAttributeMaxDynamicSharedMemorySize, GSM_TOTAL);
    cudaFuncSetAttribute((const void*)tc_gemm<3, float>,
                         cudaFuncAttributeMaxDynamicSharedMemorySize, GSM_TOTAL);

    // 0+1. LN1 (blocks 0..8191) + weight/bias prep (blocks 8192..8967), one launch
    ln1_prep_kernel<<<NTOK / 8 + 776, 256>>>(
        x, ln1_g, ln1_b, p_lnh, qkv_w, proj_w, fc1_w, fc2_w, relb, p_wth, p_biash);
    // 2. QKV -> half
    tc_gemm<0, __half><<<dim3(QKVC / 128, NTOK / 128), 256, GSM_TOTAL>>>(
        p_lnh, p_wth + WT_QKV, p_qkvh, DIM, QKVC, nullptr, nullptr);
    // 3. attention -> half
    attn_kernel<<<dim3(512, 8), 256>>>(p_qkvh, p_biash, p_attnh);
    // 4. proj + bias + residual(x) -> out fp32
    tc_gemm<3, float><<<dim3(DIM / 128, NTOK / 128), 256, GSM_TOTAL>>>(
        p_attnh, p_wth + WT_PROJ, out, DIM, DIM, proj_b, x);
    // 5. LN2 -> half
    ln_kernel<<<NTOK / 8, 256>>>(out, ln2_g, ln2_b, p_lnh);
    // 6. fc1 + bias + gelu -> half
    tc_gemm<2, __half><<<dim3(HID / 128, NTOK / 128), 256, GSM_TOTAL>>>(
        p_lnh, p_wth + WT_FC1, p_mlph, DIM, HID, fc1_b, nullptr);
    // 7. fc2 + bias + residual(out) -> out fp32
    tc_gemm<3, float><<<dim3(DIM / 128, NTOK / 128), 256, GSM_TOTAL>>>(
        p_mlph, p_wth + WT_FC2, out, HID, DIM, fc2_b, out);
}